// round 2
// baseline (speedup 1.0000x reference)
#include <cuda_runtime.h>
#include <cuda_bf16.h>
#include <math.h>

// Shapes (fixed for this problem): B=32, H=8, J=8192, K=128
// memory [B,J,K] f32, keys [B,H,K] f32, strengths [B,H,1] f32, mask [B,H,K] f32
// out [B,H,J] f32 = softmax_j( proj/(kn*mn+eps) * softplus(strength) )

#define B_ 32
#define H_ 8
#define J_ 8192
#define K_ 128
#define EPSV 1e-6f

typedef unsigned long long ull;

// scratch: exp(sharp - chunk_max) values, 32*8*8192 floats = 8 MB
__device__ float g_scratch[B_ * H_ * J_];
// per-(b,h,chunk) partials {max, sumexp}
__device__ float2 g_part[B_ * H_ * 8];

#define FMA2(d, a, b, c) asm("fma.rn.f32x2 %0, %1, %2, %3;" : "=l"(d) : "l"(a), "l"(b), "l"(c))
#define MUL2(d, a, b)    asm("mul.rn.f32x2 %0, %1, %2;"     : "=l"(d) : "l"(a), "l"(b))
#define PACK2(d, lo, hi) asm("mov.b64 %0, {%1, %2};" : "=l"(d) : "f"(lo), "f"(hi))
#define UNPACK2(lo, hi, s) asm("mov.b64 {%0, %1}, %2;" : "=f"(lo), "=f"(hi) : "l"(s))

__global__ void __launch_bounds__(256, 2)
cw_main_kernel(const float* __restrict__ memory,
               const float* __restrict__ keys,
               const float* __restrict__ strengths,
               const float* __restrict__ mask)
{
    const int b = blockIdx.y;
    const int chunk = blockIdx.x;       // 8 chunks of 1024 j
    const int tid = threadIdx.x;        // 256 threads
    const int lane = tid & 31;
    const int wid = tid >> 5;           // 8 warps

    __shared__ float s_w[K_ * H_];      // [k][h]  (float2-pairable by head)
    __shared__ float s_m2[K_ * H_];     // [k][h]
    __shared__ float s_kn[H_];
    __shared__ float s_sps[H_];
    __shared__ float s_redA[8][8];      // [warp][head]
    __shared__ float s_redB[8][8];

    // ---- coefficient prep ----
    const float* mk = mask + b * (H_ * K_);
    const float* ky = keys + b * (H_ * K_);
    for (int i = tid; i < H_ * K_; i += 256) {
        int h = i >> 7;       // i = h*128 + k
        int k = i & 127;
        float m = mk[i];
        float kv = ky[i];
        float m2 = m * m;
        s_w[k * 8 + h]  = m2 * kv;
        s_m2[k * 8 + h] = m2;
    }
    // keys_norm: warp `wid` handles head `wid`
    {
        int h = wid;
        float s = 0.f;
        #pragma unroll
        for (int kk = 0; kk < 4; ++kk) {
            int k = lane + kk * 32;
            float v = mk[h * K_ + k] * ky[h * K_ + k];
            s += v * v;
        }
        #pragma unroll
        for (int o = 16; o; o >>= 1) s += __shfl_xor_sync(0xffffffffu, s, o);
        if (lane == 0) s_kn[h] = sqrtf(s);
    }
    if (tid < H_) {
        float x = strengths[b * H_ + tid];
        s_sps[tid] = (x > 20.f) ? x : log1pf(__expf(x));
    }
    __syncthreads();

    const ull* w64 = (const ull*)s_w;   // index: k*4 + hp  (heads 2hp, 2hp+1)
    const ull* q64 = (const ull*)s_m2;

    const int j0 = chunk * 1024 + tid * 4;     // thread owns j0..j0+3
    const float* rowp = memory + ((size_t)b * J_ + j0) * K_;

    ull accP[4][4];   // [jj][hp] packed (head 2hp, 2hp+1) projection accum
    ull accN[4][4];   // norm^2 accum
    #pragma unroll
    for (int jj = 0; jj < 4; ++jj)
        #pragma unroll
        for (int hp = 0; hp < 4; ++hp) { accP[jj][hp] = 0ull; accN[jj][hp] = 0ull; }

    // ---- main K loop ----
    #pragma unroll 2
    for (int k4 = 0; k4 < 32; ++k4) {
        float mjk[4][4];
        #pragma unroll
        for (int jj = 0; jj < 4; ++jj) {
            float4 v = __ldg((const float4*)(rowp + jj * K_ + k4 * 4));
            mjk[jj][0] = v.x; mjk[jj][1] = v.y; mjk[jj][2] = v.z; mjk[jj][3] = v.w;
        }
        #pragma unroll
        for (int kk = 0; kk < 4; ++kk) {
            const int k = k4 * 4 + kk;
            ull w0 = w64[k * 4 + 0], w1 = w64[k * 4 + 1], w2 = w64[k * 4 + 2], w3 = w64[k * 4 + 3];
            ull q0 = q64[k * 4 + 0], q1 = q64[k * 4 + 1], q2 = q64[k * 4 + 2], q3 = q64[k * 4 + 3];
            #pragma unroll
            for (int jj = 0; jj < 4; ++jj) {
                float m = mjk[jj][kk];
                ull mm; PACK2(mm, m, m);
                ull ms; MUL2(ms, mm, mm);
                FMA2(accP[jj][0], w0, mm, accP[jj][0]);
                FMA2(accN[jj][0], q0, ms, accN[jj][0]);
                FMA2(accP[jj][1], w1, mm, accP[jj][1]);
                FMA2(accN[jj][1], q1, ms, accN[jj][1]);
                FMA2(accP[jj][2], w2, mm, accP[jj][2]);
                FMA2(accN[jj][2], q2, ms, accN[jj][2]);
                FMA2(accP[jj][3], w3, mm, accP[jj][3]);
                FMA2(accN[jj][3], q3, ms, accN[jj][3]);
            }
        }
    }

    // ---- epilogue: sharp = proj/(kn*sqrt(nrm2)+eps) * sps ----
    float sharp[4][8];
    #pragma unroll
    for (int jj = 0; jj < 4; ++jj) {
        #pragma unroll
        for (int hp = 0; hp < 4; ++hp) {
            float p0, p1, n0, n1;
            UNPACK2(p0, p1, accP[jj][hp]);
            UNPACK2(n0, n1, accN[jj][hp]);
            const int h0 = hp * 2, h1 = hp * 2 + 1;
            sharp[jj][h0] = p0 / (s_kn[h0] * sqrtf(n0) + EPSV) * s_sps[h0];
            sharp[jj][h1] = p1 / (s_kn[h1] * sqrtf(n1) + EPSV) * s_sps[h1];
        }
    }

    // ---- chunk-level softmax partials (per head) ----
    float cmax[8];
    #pragma unroll
    for (int h = 0; h < 8; ++h) {
        float t = fmaxf(fmaxf(sharp[0][h], sharp[1][h]), fmaxf(sharp[2][h], sharp[3][h]));
        #pragma unroll
        for (int o = 16; o; o >>= 1) t = fmaxf(t, __shfl_xor_sync(0xffffffffu, t, o));
        if (lane == 0) s_redA[wid][h] = t;
    }
    __syncthreads();
    #pragma unroll
    for (int h = 0; h < 8; ++h) {
        float t = s_redA[0][h];
        #pragma unroll
        for (int w = 1; w < 8; ++w) t = fmaxf(t, s_redA[w][h]);
        cmax[h] = t;
    }

    float e[4][8];
    float csum[8];
    #pragma unroll
    for (int h = 0; h < 8; ++h) {
        float t = 0.f;
        #pragma unroll
        for (int jj = 0; jj < 4; ++jj) {
            float ev = __expf(sharp[jj][h] - cmax[h]);
            e[jj][h] = ev;
            t += ev;
        }
        #pragma unroll
        for (int o = 16; o; o >>= 1) t += __shfl_xor_sync(0xffffffffu, t, o);
        if (lane == 0) s_redB[wid][h] = t;
    }
    __syncthreads();
    #pragma unroll
    for (int h = 0; h < 8; ++h) {
        float t = 0.f;
        #pragma unroll
        for (int w = 0; w < 8; ++w) t += s_redB[w][h];
        csum[h] = t;
    }

    if (tid == 0) {
        #pragma unroll
        for (int h = 0; h < 8; ++h)
            g_part[(b * H_ + h) * 8 + chunk] = make_float2(cmax[h], csum[h]);
    }

    // ---- store exp(sharp - cmax) to scratch ----
    #pragma unroll
    for (int h = 0; h < 8; ++h) {
        float4 v = make_float4(e[0][h], e[1][h], e[2][h], e[3][h]);
        *(float4*)(g_scratch + (size_t)(b * H_ + h) * J_ + j0) = v;
    }
}

__global__ void __launch_bounds__(256)
cw_finalize_kernel(float* __restrict__ out)
{
    const int x = blockIdx.x;   // b*8 + h, 256 rows
    const int tid = threadIdx.x;

    __shared__ float s_scale[8];
    if (tid == 0) {
        float m[8], s[8];
        #pragma unroll
        for (int c = 0; c < 8; ++c) {
            float2 p = g_part[x * 8 + c];
            m[c] = p.x; s[c] = p.y;
        }
        float M = m[0];
        #pragma unroll
        for (int c = 1; c < 8; ++c) M = fmaxf(M, m[c]);
        float S = 0.f;
        #pragma unroll
        for (int c = 0; c < 8; ++c) S += s[c] * __expf(m[c] - M);
        float inv = 1.f / S;
        #pragma unroll
        for (int c = 0; c < 8; ++c) s_scale[c] = __expf(m[c] - M) * inv;
    }
    __syncthreads();

    const float4* src = (const float4*)(g_scratch + (size_t)x * J_);
    float4* dst = (float4*)(out + (size_t)x * J_);
    #pragma unroll
    for (int it = 0; it < 8; ++it) {
        int i = it * 256 + tid;              // 2048 float4 per row
        float sc = s_scale[i >> 8];          // 256 float4 = 1024 floats per chunk
        float4 v = src[i];
        dst[i] = make_float4(v.x * sc, v.y * sc, v.z * sc, v.w * sc);
    }
}

extern "C" void kernel_launch(void* const* d_in, const int* in_sizes, int n_in,
                              void* d_out, int out_size)
{
    const float* memory    = (const float*)d_in[0];
    const float* keys      = (const float*)d_in[1];
    const float* strengths = (const float*)d_in[2];
    const float* mask      = (const float*)d_in[3];
    float* out = (float*)d_out;

    cw_main_kernel<<<dim3(8, B_), 256>>>(memory, keys, strengths, mask);
    cw_finalize_kernel<<<B_ * H_, 256>>>(out);
}